// round 7
// baseline (speedup 1.0000x reference)
#include <cuda_runtime.h>
#include <cuda_fp16.h>
#include <math.h>

#define L_SEQ 2048
#define H_DIM 2048
#define G3H   6144
#define NCTA  128
#define TPB   512     // 16 warps; warp w owns j = cta*16 + w
#define FLAG_STRIDE 8 // words between per-CTA flags (32B spacing)

// -------- device-global scratch (no allocations allowed) --------
__device__ float g_gi[(size_t)L_SEQ * G3H];         // 48 MB: x@W_ih^T + b_ih (+ b_hh for r,z)
__device__ __align__(16) __half g_h16[2][H_DIM];    // double-buffered fp16 h broadcast
__device__ unsigned int g_hflag[NCTA * FLAG_STRIDE];// per-CTA progress flags (step count)

__device__ __forceinline__ __half2 u2h2(unsigned u) {
    return *reinterpret_cast<__half2*>(&u);
}

// fast sigmoid / tanh via MUFU (ex2 + rcp), rel err ~1e-6
__device__ __forceinline__ float fsig(float x) {
    float e, r;
    asm("ex2.approx.ftz.f32 %0, %1;" : "=f"(e) : "f"(-1.4426950408889634f * x));
    asm("rcp.approx.ftz.f32 %0, %1;" : "=f"(r) : "f"(1.0f + e));
    return r;
}
__device__ __forceinline__ float ftanh(float x) {
    float e, r;
    asm("ex2.approx.ftz.f32 %0, %1;" : "=f"(e) : "f"(2.8853900817779268f * x));  // e^(2x)
    asm("rcp.approx.ftz.f32 %0, %1;" : "=f"(r) : "f"(1.0f + e));
    return 1.0f - 2.0f * r;
}

// ============================================================
// Kernel A: g_gi[t][r] = x[t]·w_ih[r] + b_ih[r] + (r<2H ? b_hh[r] : 0)
// 128x128x16 tile, 256 threads, 8x8 per thread, f32x2 FMAs.
// Block (0,0) also zeroes the per-CTA flags for this launch.
// ============================================================
#define BM 128
#define BN 128
#define BK 16
#define BPAD 4

__global__ void __launch_bounds__(256, 2) gemm_gi_kernel(const float* __restrict__ X,
                                                         const float* __restrict__ W,
                                                         const float* __restrict__ b_ih,
                                                         const float* __restrict__ b_hh) {
    if (blockIdx.x == 0 && blockIdx.y == 0) {
#pragma unroll
        for (int i = 0; i < 4; i++)
            g_hflag[threadIdx.x + i * 256] = 0u;    // 1024 words
    }

    __shared__ float As[BK][BM + BPAD];
    __shared__ float Bs[BK][BN + BPAD];
    const int K = H_DIM;
    const int bm = blockIdx.y * BM;
    const int bn = blockIdx.x * BN;
    const int tid = threadIdx.x;
    const int tm = tid >> 4;          // 0..15
    const int tn = tid & 15;          // 0..15

    unsigned long long c[8][4];
#pragma unroll
    for (int i = 0; i < 8; i++)
#pragma unroll
        for (int jj = 0; jj < 4; jj++) c[i][jj] = 0ull;

    const int lrow = tid >> 1;        // 0..127
    const int lk8  = (tid & 1) * 8;   // 0 or 8

    for (int k0 = 0; k0 < K; k0 += BK) {
        float4 a0 = *reinterpret_cast<const float4*>(&X[(size_t)(bm + lrow) * K + k0 + lk8]);
        float4 a1 = *reinterpret_cast<const float4*>(&X[(size_t)(bm + lrow) * K + k0 + lk8 + 4]);
        float4 b0 = *reinterpret_cast<const float4*>(&W[(size_t)(bn + lrow) * K + k0 + lk8]);
        float4 b1 = *reinterpret_cast<const float4*>(&W[(size_t)(bn + lrow) * K + k0 + lk8 + 4]);
        As[lk8 + 0][lrow] = a0.x; As[lk8 + 1][lrow] = a0.y;
        As[lk8 + 2][lrow] = a0.z; As[lk8 + 3][lrow] = a0.w;
        As[lk8 + 4][lrow] = a1.x; As[lk8 + 5][lrow] = a1.y;
        As[lk8 + 6][lrow] = a1.z; As[lk8 + 7][lrow] = a1.w;
        Bs[lk8 + 0][lrow] = b0.x; Bs[lk8 + 1][lrow] = b0.y;
        Bs[lk8 + 2][lrow] = b0.z; Bs[lk8 + 3][lrow] = b0.w;
        Bs[lk8 + 4][lrow] = b1.x; Bs[lk8 + 5][lrow] = b1.y;
        Bs[lk8 + 6][lrow] = b1.z; Bs[lk8 + 7][lrow] = b1.w;
        __syncthreads();
#pragma unroll
        for (int k = 0; k < BK; k++) {
            float4 av0 = *reinterpret_cast<const float4*>(&As[k][tm << 3]);
            float4 av1 = *reinterpret_cast<const float4*>(&As[k][(tm << 3) + 4]);
            float4 bv0 = *reinterpret_cast<const float4*>(&Bs[k][tn << 3]);
            float4 bv1 = *reinterpret_cast<const float4*>(&Bs[k][(tn << 3) + 4]);
            unsigned long long bp[4];
            bp[0] = reinterpret_cast<const unsigned long long*>(&bv0)[0];
            bp[1] = reinterpret_cast<const unsigned long long*>(&bv0)[1];
            bp[2] = reinterpret_cast<const unsigned long long*>(&bv1)[0];
            bp[3] = reinterpret_cast<const unsigned long long*>(&bv1)[1];
            float av[8] = {av0.x, av0.y, av0.z, av0.w, av1.x, av1.y, av1.z, av1.w};
#pragma unroll
            for (int i = 0; i < 8; i++) {
                unsigned long long asp;
                asm("mov.b64 %0, {%1, %1};" : "=l"(asp) : "r"(__float_as_uint(av[i])));
#pragma unroll
                for (int jj = 0; jj < 4; jj++)
                    asm("fma.rn.f32x2 %0, %1, %2, %0;" : "+l"(c[i][jj]) : "l"(asp), "l"(bp[jj]));
            }
        }
        __syncthreads();
    }

#pragma unroll
    for (int i = 0; i < 8; i++) {
        int row = bm + (tm << 3) + i;
#pragma unroll
        for (int jj = 0; jj < 4; jj++) {
            unsigned lo, hi;
            asm("mov.b64 {%0, %1}, %2;" : "=r"(lo), "=r"(hi) : "l"(c[i][jj]));
            int col = bn + (tn << 3) + 2 * jj;
            float bs0 = b_ih[col]     + ((col     < 2 * H_DIM) ? b_hh[col]     : 0.0f);
            float bs1 = b_ih[col + 1] + ((col + 1 < 2 * H_DIM) ? b_hh[col + 1] : 0.0f);
            float2 v = make_float2(__uint_as_float(lo) + bs0, __uint_as_float(hi) + bs1);
            *reinterpret_cast<float2*>(&g_gi[(size_t)row * G3H + col]) = v;
        }
    }
}

// ============================================================
// Kernel B: persistent GRU recurrence.
// 128 CTAs x 512 threads (16 warps). Warp w owns j = cta*16 + w:
// 3 gate rows, weights in 96 half2 registers per lane.
// Per step: lane0 gi prefetch -> consumers (tid<256) poll per-CTA
// flag + fetch own uint4 of h -> bar -> reg matvec (32-MAC fp16
// chains) -> butterfly reduce -> lane0 fast gates -> h to SMEM ->
// bar -> tid0 vectorized publish (2x STG.128.cg + release flag) ->
// lane0 out store (off critical path).
// ============================================================
__global__ void __launch_bounds__(TPB, 1) gru_kernel(const float* __restrict__ w_hh,
                                                     const float* __restrict__ b_hh,
                                                     float* __restrict__ out,
                                                     int out_elems) {
    __shared__ uint4 sH[H_DIM / 8];                       // 4KB h_t
    __shared__ __align__(16) unsigned short sNewH[16];    // this CTA's new h (fp16)

    const int tid  = threadIdx.x;
    const int warp = tid >> 5;
    const int lane = tid & 31;
    const int cta  = blockIdx.x;
    const int j    = cta * 16 + warp;

    // ---- prologue: 3 rows of W_hh into 96 half2 registers ----
    __half2 w[3][8][4];
#pragma unroll
    for (int g = 0; g < 3; g++) {
        const float* wr = w_hh + (size_t)(g * H_DIM + j) * H_DIM;
#pragma unroll
        for (int i = 0; i < 8; i++) {
            int k = i * 256 + lane * 8;
            float4 a = *reinterpret_cast<const float4*>(wr + k);
            float4 b = *reinterpret_cast<const float4*>(wr + k + 4);
            w[g][i][0] = __floats2half2_rn(a.x, a.y);
            w[g][i][1] = __floats2half2_rn(a.z, a.w);
            w[g][i][2] = __floats2half2_rn(b.x, b.y);
            w[g][i][3] = __floats2half2_rn(b.z, b.w);
        }
    }

    float h_own = 0.0f;
    const float bhn = (lane == 0) ? b_hh[2 * H_DIM + j] : 0.0f;
    const float* gi_ptr  = g_gi + j;
    float*       out_ptr = out + j;
    const unsigned int* my_flag = &g_hflag[(tid >> 1) * FLAG_STRIDE];

    // ================= step 0 (h = 0, no poll) =================
    if (lane == 0) {
        float ir  = gi_ptr[0];
        float iz  = gi_ptr[H_DIM];
        float inn = gi_ptr[2 * H_DIM];
        float rg = fsig(ir);
        float zg = fsig(iz);
        float ng = ftanh(inn + rg * bhn);
        h_own = (1.0f - zg) * ng;
        sNewH[warp] = (unsigned short)__half_as_ushort(__float2half(h_own));
    }
    __syncthreads();
    if (tid == 0) {
        uint4 lo = *reinterpret_cast<const uint4*>(&sNewH[0]);
        uint4 hi = *reinterpret_cast<const uint4*>(&sNewH[8]);
        __half* dst = &g_h16[1][cta * 16];
        asm volatile("st.global.cg.v4.u32 [%0], {%1,%2,%3,%4};"
                     :: "l"(dst), "r"(lo.x), "r"(lo.y), "r"(lo.z), "r"(lo.w) : "memory");
        asm volatile("st.global.cg.v4.u32 [%0], {%1,%2,%3,%4};"
                     :: "l"(dst + 8), "r"(hi.x), "r"(hi.y), "r"(hi.z), "r"(hi.w) : "memory");
        asm volatile("st.release.gpu.global.u32 [%0], %1;"
                     :: "l"(&g_hflag[cta * FLAG_STRIDE]), "r"(1u) : "memory");
    }
    if (lane == 0) out_ptr[0] = h_own;
    gi_ptr  += G3H;
    out_ptr += H_DIM;

    // ================= steps 1..L-1 =================
    for (int t = 1; t < L_SEQ; t++) {
        // ---- gi prefetch (lands while polling) ----
        float ir = 0.f, iz = 0.f, inn = 0.f;
        if (lane == 0) {
            ir  = gi_ptr[0];
            iz  = gi_ptr[H_DIM];
            inn = gi_ptr[2 * H_DIM];
        }

        // ---- fused wait + fetch ----
        if (tid < H_DIM / 8) {
            const unsigned tg = (unsigned)t;
            unsigned v;
            do {
                asm volatile("ld.acquire.gpu.global.u32 %0, [%1];"
                             : "=r"(v) : "l"(my_flag) : "memory");
            } while (v < tg);
            sH[tid] = __ldcg(reinterpret_cast<const uint4*>(&g_h16[t & 1][0]) + tid);
        }
        __syncthreads();

        // ---- matvec: 3 rows, 32-MAC fp16 chains, flush to fp32 ----
        float acc[3] = {0.f, 0.f, 0.f};
#pragma unroll
        for (int ii = 0; ii < 2; ii++) {
            const int base = ii * 4;
            uint4 p = sH[(base + 0) * 32 + lane];
            uint4 q = sH[(base + 1) * 32 + lane];
            __half2 s[3];
#pragma unroll
            for (int g = 0; g < 3; g++) {
                __half2 t0 = __hmul2(w[g][base + 0][0], u2h2(p.x));
                t0 = __hfma2(w[g][base + 0][1], u2h2(p.y), t0);
                t0 = __hfma2(w[g][base + 0][2], u2h2(p.z), t0);
                t0 = __hfma2(w[g][base + 0][3], u2h2(p.w), t0);
                t0 = __hfma2(w[g][base + 1][0], u2h2(q.x), t0);
                t0 = __hfma2(w[g][base + 1][1], u2h2(q.y), t0);
                t0 = __hfma2(w[g][base + 1][2], u2h2(q.z), t0);
                t0 = __hfma2(w[g][base + 1][3], u2h2(q.w), t0);
                s[g] = t0;
            }
            p = sH[(base + 2) * 32 + lane];
            q = sH[(base + 3) * 32 + lane];
#pragma unroll
            for (int g = 0; g < 3; g++) {
                __half2 t0 = s[g];
                t0 = __hfma2(w[g][base + 2][0], u2h2(p.x), t0);
                t0 = __hfma2(w[g][base + 2][1], u2h2(p.y), t0);
                t0 = __hfma2(w[g][base + 2][2], u2h2(p.z), t0);
                t0 = __hfma2(w[g][base + 2][3], u2h2(p.w), t0);
                t0 = __hfma2(w[g][base + 3][0], u2h2(q.x), t0);
                t0 = __hfma2(w[g][base + 3][1], u2h2(q.y), t0);
                t0 = __hfma2(w[g][base + 3][2], u2h2(q.z), t0);
                t0 = __hfma2(w[g][base + 3][3], u2h2(q.w), t0);
                float2 f = __half22float2(t0);
                acc[g] += f.x + f.y;
            }
        }

        // ---- butterfly reduce over 32 lanes ----
#pragma unroll
        for (int off = 16; off; off >>= 1) {
#pragma unroll
            for (int g = 0; g < 3; g++)
                acc[g] += __shfl_xor_sync(0xffffffffu, acc[g], off);
        }

        // ---- gates (lane 0, fast MUFU path) ----
        if (lane == 0) {
            float rg = fsig(ir + acc[0]);
            float zg = fsig(iz + acc[1]);
            float ng = ftanh(inn + rg * (acc[2] + bhn));
            float hn = (1.0f - zg) * ng + zg * h_own;
            h_own = hn;
            sNewH[warp] = (unsigned short)__half_as_ushort(__float2half(hn));
        }
        __syncthreads();

        // ---- vectorized publish: 32B h store + release flag (tid0) ----
        if (tid == 0) {
            uint4 lo = *reinterpret_cast<const uint4*>(&sNewH[0]);
            uint4 hi = *reinterpret_cast<const uint4*>(&sNewH[8]);
            __half* dst = &g_h16[(t + 1) & 1][cta * 16];
            asm volatile("st.global.cg.v4.u32 [%0], {%1,%2,%3,%4};"
                         :: "l"(dst), "r"(lo.x), "r"(lo.y), "r"(lo.z), "r"(lo.w) : "memory");
            asm volatile("st.global.cg.v4.u32 [%0], {%1,%2,%3,%4};"
                         :: "l"(dst + 8), "r"(hi.x), "r"(hi.y), "r"(hi.z), "r"(hi.w) : "memory");
            asm volatile("st.release.gpu.global.u32 [%0], %1;"
                         :: "l"(&g_hflag[cta * FLAG_STRIDE]), "r"((unsigned)(t + 1)) : "memory");
        }
        // ---- out store: after bar, off the release drain ----
        if (lane == 0) out_ptr[0] = h_own;

        gi_ptr  += G3H;
        out_ptr += H_DIM;
    }

    // ---- final hidden state (both tails of d_out) ----
    if (lane == 0) {
        size_t base = (size_t)L_SEQ * H_DIM;
        if ((long long)(base + j) < (long long)out_elems)          out[base + j] = h_own;
        if ((long long)(base + H_DIM + j) < (long long)out_elems)  out[base + H_DIM + j] = h_own;
    }
}

// ============================================================
extern "C" void kernel_launch(void* const* d_in, const int* in_sizes, int n_in,
                              void* d_out, int out_size) {
    const float* x    = (const float*)d_in[0];
    const float* w_ih = (const float*)d_in[1];
    const float* w_hh = (const float*)d_in[2];
    const float* b_ih = (const float*)d_in[3];
    const float* b_hh = (const float*)d_in[4];
    float* out = (float*)d_out;

    gemm_gi_kernel<<<dim3(G3H / BN, L_SEQ / BM), 256>>>(x, w_ih, b_ih, b_hh);
    gru_kernel<<<NCTA, TPB>>>(w_hh, b_hh, out, out_size);
}